// round 13
// baseline (speedup 1.0000x reference)
#include <cuda_runtime.h>
#include <cuda_bf16.h>
#include <cstdint>

// Problem constants
#define B_  4
#define S_  2048
#define D_  1024
#define H_  16
#define DK_ 64

static const long long BS_LL   = (long long)B_ * S_;           // 8192
static const long long BSD_LL  = (long long)B_ * S_ * D_;      // 8388608
static const long long ATTN_LL = (long long)B_ * H_ * S_ * S_; // 268435456

// Scratch (allocation-free rule: __device__ globals)
__device__ float          g_q[(size_t)BSD_LL];    // Qp fp32; reused as Ctx fp32
__device__ __nv_bfloat16  g_kh[(size_t)BSD_LL], g_kl[(size_t)BSD_LL];   // Kp hi/lo
__device__ __nv_bfloat16  g_vth[(size_t)BSD_LL], g_vtl[(size_t)BSD_LL]; // Vt hi/lo [B][H][DK][S]
__device__ __nv_bfloat16  g_wh[4u * 1024u * 1024u], g_wl[4u * 1024u * 1024u];
__device__ float          g_attn_fallback[(size_t)ATTN_LL];

__device__ __forceinline__ uint32_t smem_u32(const void* p) {
    uint32_t a;
    asm("{ .reg .u64 t; cvta.to.shared.u64 t, %1; cvt.u32.u64 %0, t; }" : "=r"(a) : "l"(p));
    return a;
}
__device__ __forceinline__ void ldmx4(uint32_t* r, uint32_t addr) {
    asm volatile("ldmatrix.sync.aligned.m8n8.x4.shared.b16 {%0,%1,%2,%3}, [%4];"
                 : "=r"(r[0]), "=r"(r[1]), "=r"(r[2]), "=r"(r[3]) : "r"(addr));
}
__device__ __forceinline__ void ldmx2(uint32_t* r, uint32_t addr) {
    asm volatile("ldmatrix.sync.aligned.m8n8.x2.shared.b16 {%0,%1}, [%2];"
                 : "=r"(r[0]), "=r"(r[1]) : "r"(addr));
}
__device__ __forceinline__ void mma16816(float* c, const uint32_t* a, const uint32_t* b) {
    asm volatile(
        "mma.sync.aligned.m16n8k16.row.col.f32.bf16.bf16.f32 "
        "{%0,%1,%2,%3}, {%4,%5,%6,%7}, {%8,%9}, {%0,%1,%2,%3};"
        : "+f"(c[0]), "+f"(c[1]), "+f"(c[2]), "+f"(c[3])
        : "r"(a[0]), "r"(a[1]), "r"(a[2]), "r"(a[3]), "r"(b[0]), "r"(b[1]));
}
__device__ __forceinline__ void sts64(uint32_t addr, uint2 v) {
    asm volatile("st.shared.v2.b32 [%0], {%1, %2};" :: "r"(addr), "r"(v.x), "r"(v.y) : "memory");
}

// Split a float4 into packed bf16 hi (truncation, exact) and lo (remainder).
__device__ __forceinline__ void split4(const float4& v, uint2& hi, uint2& lo) {
    uint32_t ux = __float_as_uint(v.x), uy = __float_as_uint(v.y);
    uint32_t uz = __float_as_uint(v.z), uw = __float_as_uint(v.w);
    hi.x = (ux >> 16) | (uy & 0xFFFF0000u);
    hi.y = (uz >> 16) | (uw & 0xFFFF0000u);
    float lx = v.x - __uint_as_float(ux & 0xFFFF0000u);
    float ly = v.y - __uint_as_float(uy & 0xFFFF0000u);
    float lz = v.z - __uint_as_float(uz & 0xFFFF0000u);
    float lw = v.w - __uint_as_float(uw & 0xFFFF0000u);
    __nv_bfloat162 l0 = __floats2bfloat162_rn(lx, ly);
    __nv_bfloat162 l1 = __floats2bfloat162_rn(lz, lw);
    lo.x = *reinterpret_cast<uint32_t*>(&l0);
    lo.y = *reinterpret_cast<uint32_t*>(&l1);
}
// Pack hi bf16 (truncation) of two floats into one u32 (low half = first elem).
__device__ __forceinline__ uint32_t pack_hi(float2 v) {
    return (__float_as_uint(v.x) >> 16) | (__float_as_uint(v.y) & 0xFFFF0000u);
}
__device__ __forceinline__ uint32_t pack_lo(float2 v) {
    float hx = __uint_as_float(__float_as_uint(v.x) & 0xFFFF0000u);
    float hy = __uint_as_float(__float_as_uint(v.y) & 0xFFFF0000u);
    __nv_bfloat162 l = __floats2bfloat162_rn(v.x - hx, v.y - hy);
    return *reinterpret_cast<uint32_t*>(&l);
}

// fp32 -> bf16 hi/lo split (vectorized), for weights
__global__ __launch_bounds__(256) void split_f32(
    const float* __restrict__ src, __nv_bfloat16* __restrict__ dh,
    __nv_bfloat16* __restrict__ dl, int n4)
{
    int i = blockIdx.x * 256 + threadIdx.x;
    if (i >= n4) return;
    float4 v = reinterpret_cast<const float4*>(src)[i];
    uint2 h, l;
    split4(v, h, l);
    reinterpret_cast<uint2*>(dh)[i] = h;
    reinterpret_cast<uint2*>(dl)[i] = l;
}

// ---------------------------------------------------------------------------
// bf16-split GEMM: C[m,n] = scale * sum_k A[m,k]*B[n,k] (+ bias[n])
//  A fp32 (split in-loop, R6-verified path), B pre-split bf16 hi/lo.
//  2-stage smem double buffer, 1 sync/iter, ldmatrix everywhere.
//  EPI: 0 = fp32 C; 1 = bf16 hi/lo Ch/Cl; 2 = bf16 hi/lo transposed per-head.
// ---------------------------------------------------------------------------
template <int BN, int EPI>
__global__ __launch_bounds__(256) void gemm_mma(
    const float* __restrict__ A,
    const __nv_bfloat16* __restrict__ Bh, const __nv_bfloat16* __restrict__ Bl,
    const float* __restrict__ bias,
    float* __restrict__ C, __nv_bfloat16* __restrict__ Ch, __nv_bfloat16* __restrict__ Cl,
    int K, int lda, int ldb, int ldc,
    long long sAb, long long sAh, long long sBb, long long sBhh,
    long long sCb, long long sChh, int Hdim, float scale)
{
    constexpr int BM = 128, BK = 32;
    constexpr int SK = 40;                       // smem row stride in halves
    constexpr int NBB = BN / 64;                 // B uint4 loads per thread per array
    constexpr int WGM = (BN == 128) ? 2 : 4;
    constexpr int WGN = (BN == 128) ? 4 : 2;
    constexpr int WM = BM / WGM, WN = BN / WGN;
    constexpr int MF = WM / 16, NF = WN / 8;
    constexpr uint32_t OFF_AL = BM * SK * 2;
    constexpr uint32_t OFF_BH = 2u * BM * SK * 2;
    constexpr uint32_t OFF_BL = OFF_BH + BN * SK * 2;
    constexpr uint32_t STAGE  = OFF_BL + BN * SK * 2;

    extern __shared__ char sm_raw[];
    const uint32_t sbase = smem_u32(sm_raw);

    const int bz = blockIdx.z;
    const int bi = bz / Hdim, hz = bz % Hdim;
    A  += (long long)bi * sAb + (long long)hz * sAh;
    Bh += (long long)bi * sBb + (long long)hz * sBhh;
    Bl += (long long)bi * sBb + (long long)hz * sBhh;
    if (EPI == 0) C += (long long)bi * sCb + (long long)hz * sChh;

    const int tid = threadIdx.x;
    const int wid = tid >> 5, lane = tid & 31;
    const int wm = (BN == 128) ? (wid >> 2) : (wid >> 1);
    const int wn = (BN == 128) ? (wid & 3) : (wid & 1);
    const int row0 = blockIdx.y * BM;
    const int col0 = blockIdx.x * BN;

    float acc[MF][NF][4];
#pragma unroll
    for (int i = 0; i < MF; i++)
#pragma unroll
        for (int j = 0; j < NF; j++)
#pragma unroll
            for (int c = 0; c < 4; c++) acc[i][j][c] = 0.0f;

    // ldmatrix per-thread row assignments (R6-verified)
    const int a_row = wm * WM + (lane & 15);        // + mf*16
    const int a_kof = 8 * (lane >> 4);
    const int b_row = wn * WN + (lane & 7);         // + nf*8
    const int b_kof = 8 * ((lane >> 3) & 1);

    // staging assignments
    const int sa_r = tid >> 3, sa_c = (tid & 7) * 4;   // A: +j*32 rows, col in elems
    const int sb_r = tid >> 2, sb_c = (tid & 3) * 8;   // B: +j*64 rows, col in halves

    float4 a4[4];
    uint4  bh4[NBB], bl4[NBB];

#define LOAD_A(KT)                                                              \
    _Pragma("unroll")                                                           \
    for (int j = 0; j < 4; j++) {                                               \
        a4[j] = *reinterpret_cast<const float4*>(                               \
            A + (long long)(row0 + sa_r + j * 32) * lda + (KT) + sa_c);         \
    }
#define LOAD_B(KT)                                                              \
    _Pragma("unroll")                                                           \
    for (int j = 0; j < NBB; j++) {                                             \
        bh4[j] = *reinterpret_cast<const uint4*>(                               \
            Bh + (long long)(col0 + sb_r + j * 64) * ldb + (KT) + sb_c);        \
        bl4[j] = *reinterpret_cast<const uint4*>(                               \
            Bl + (long long)(col0 + sb_r + j * 64) * ldb + (KT) + sb_c);        \
    }
#define STORE_STAGE(S)                                                          \
    {                                                                           \
        const uint32_t sb = sbase + (uint32_t)(S) * STAGE;                      \
        _Pragma("unroll")                                                       \
        for (int j = 0; j < 4; j++) {                                           \
            uint2 h, l; split4(a4[j], h, l);                                    \
            uint32_t o = ((sa_r + j * 32) * SK + sa_c) * 2;                     \
            sts64(sb + o, h);                                                   \
            sts64(sb + OFF_AL + o, l);                                          \
        }                                                                       \
        _Pragma("unroll")                                                       \
        for (int j = 0; j < NBB; j++) {                                         \
            uint32_t o = ((sb_r + j * 64) * SK + sb_c) * 2;                     \
            sts64(sb + OFF_BH + o, make_uint2(bh4[j].x, bh4[j].y));             \
            sts64(sb + OFF_BH + o + 8, make_uint2(bh4[j].z, bh4[j].w));         \
            sts64(sb + OFF_BL + o, make_uint2(bl4[j].x, bl4[j].y));             \
            sts64(sb + OFF_BL + o + 8, make_uint2(bl4[j].z, bl4[j].w));         \
        }                                                                       \
    }

    const int nIter = K / BK;

    // Preamble: tile 0 -> stage 0; tile 1 -> regs
    LOAD_A(0); LOAD_B(0);
    STORE_STAGE(0);
    if (nIter > 1) { LOAD_A(BK); LOAD_B(BK); }
    __syncthreads();

    for (int i = 0; i < nIter; i++) {
        const int s = i & 1;
        if (i + 1 < nIter) STORE_STAGE(s ^ 1);           // STS drains during MMA
        if (i + 2 < nIter) { LOAD_A((i + 2) * BK); LOAD_B((i + 2) * BK); }

        const uint32_t sb = sbase + (uint32_t)s * STAGE;
#pragma unroll
        for (int ks = 0; ks < 2; ks++) {
            const int k16 = ks * 16;
            uint32_t bhf[NF][2], blf[NF][2];
#pragma unroll
            for (int nf = 0; nf < NF; nf++) {
                uint32_t off = ((b_row + nf * 8) * SK + k16 + b_kof) * 2;
                ldmx2(bhf[nf], sb + OFF_BH + off);
                ldmx2(blf[nf], sb + OFF_BL + off);
            }
#pragma unroll
            for (int mf = 0; mf < MF; mf++) {
                uint32_t ah[4], al[4];
                uint32_t off = ((a_row + mf * 16) * SK + k16 + a_kof) * 2;
                ldmx4(ah, sb + off);
                ldmx4(al, sb + OFF_AL + off);
#pragma unroll
                for (int nf = 0; nf < NF; nf++) {
                    mma16816(acc[mf][nf], ah, bhf[nf]);   // hi*hi
                    mma16816(acc[mf][nf], al, bhf[nf]);   // lo*hi
                    mma16816(acc[mf][nf], ah, blf[nf]);   // hi*lo
                }
            }
        }
        __syncthreads();
    }
#undef LOAD_A
#undef LOAD_B
#undef STORE_STAGE

    // Epilogue
#pragma unroll
    for (int mf = 0; mf < MF; mf++) {
#pragma unroll
        for (int nf = 0; nf < NF; nf++) {
            const int rg = row0 + wm * WM + mf * 16 + (lane >> 2);
            const int cg = col0 + wn * WN + nf * 8 + 2 * (lane & 3);
            float2 v0, v1;
            v0.x = acc[mf][nf][0] * scale; v0.y = acc[mf][nf][1] * scale;
            v1.x = acc[mf][nf][2] * scale; v1.y = acc[mf][nf][3] * scale;
            if (bias) {
                float bx = __ldg(bias + cg), by = __ldg(bias + cg + 1);
                v0.x += bx; v0.y += by; v1.x += bx; v1.y += by;
            }
            if (EPI == 0) {
                *reinterpret_cast<float2*>(C + (long long)rg * ldc + cg) = v0;
                *reinterpret_cast<float2*>(C + (long long)(rg + 8) * ldc + cg) = v1;
            } else if (EPI == 1) {
                *reinterpret_cast<uint32_t*>(Ch + (long long)rg * ldc + cg) = pack_hi(v0);
                *reinterpret_cast<uint32_t*>(Cl + (long long)rg * ldc + cg) = pack_lo(v0);
                *reinterpret_cast<uint32_t*>(Ch + (long long)(rg + 8) * ldc + cg) = pack_hi(v1);
                *reinterpret_cast<uint32_t*>(Cl + (long long)(rg + 8) * ldc + cg) = pack_lo(v1);
            } else {
                // transposed per-head: [((b*H + h)*DK + d)*S + s]   (R6-verified indexing)
                float vv[4] = {v0.x, v0.y, v1.x, v1.y};
#pragma unroll
                for (int e = 0; e < 4; e++) {
                    const int r = rg + (e >> 1) * 8;
                    const int n = cg + (e & 1);
                    const int b = r >> 11, ss = r & 2047;
                    const long long idx =
                        (((long long)(b * H_ + (n >> 6)) * DK_ + (n & 63)) << 11) + ss;
                    float x = vv[e];
                    uint32_t ux = __float_as_uint(x);
                    Ch[idx] = __ushort_as_bfloat16((unsigned short)(ux >> 16));
                    Cl[idx] = __float2bfloat16(x - __uint_as_float(ux & 0xFFFF0000u));
                }
            }
        }
    }
}

// ---------------------------------------------------------------------------
// Row softmax, row length 2048, register-resident.
// ---------------------------------------------------------------------------
__global__ __launch_bounds__(256) void softmax_rows2048(float* __restrict__ att)
{
    float4* p4 = reinterpret_cast<float4*>(att + (long long)blockIdx.x * 2048);
    const int tid = threadIdx.x;
    __shared__ float red[32];

    float4 v0 = p4[tid];
    float4 v1 = p4[tid + 256];

    float m = fmaxf(fmaxf(fmaxf(v0.x, v0.y), fmaxf(v0.z, v0.w)),
                    fmaxf(fmaxf(v1.x, v1.y), fmaxf(v1.z, v1.w)));
#pragma unroll
    for (int o = 16; o > 0; o >>= 1) m = fmaxf(m, __shfl_xor_sync(0xffffffffu, m, o));
    if ((tid & 31) == 0) red[tid >> 5] = m;
    __syncthreads();
    if (tid < 32) {
        float t = red[tid & 7];
#pragma unroll
        for (int o = 4; o > 0; o >>= 1) t = fmaxf(t, __shfl_xor_sync(0xffffffffu, t, o));
        red[tid & 7] = t;
    }
    __syncthreads();
    m = red[0];

    v0.x = __expf(v0.x - m); v0.y = __expf(v0.y - m);
    v0.z = __expf(v0.z - m); v0.w = __expf(v0.w - m);
    v1.x = __expf(v1.x - m); v1.y = __expf(v1.y - m);
    v1.z = __expf(v1.z - m); v1.w = __expf(v1.w - m);
    float s = v0.x + v0.y + v0.z + v0.w + v1.x + v1.y + v1.z + v1.w;
#pragma unroll
    for (int o = 16; o > 0; o >>= 1) s += __shfl_xor_sync(0xffffffffu, s, o);
    __syncthreads();
    if ((tid & 31) == 0) red[tid >> 5] = s;
    __syncthreads();
    if (tid < 32) {
        float t = red[tid & 7];
#pragma unroll
        for (int o = 4; o > 0; o >>= 1) t += __shfl_xor_sync(0xffffffffu, t, o);
        red[tid & 7] = t;
    }
    __syncthreads();
    const float inv = 1.0f / red[0];

    v0.x *= inv; v0.y *= inv; v0.z *= inv; v0.w *= inv;
    v1.x *= inv; v1.y *= inv; v1.z *= inv; v1.w *= inv;
    p4[tid] = v0;
    p4[tid + 256] = v1;
}

extern "C" void kernel_launch(void* const* d_in, const int* in_sizes, int n_in,
                              void* d_out, int out_size)
{
    const float* q  = (const float*)d_in[0];
    const float* k  = (const float*)d_in[1];
    const float* v  = (const float*)d_in[2];
    const float* Wq = (const float*)d_in[3];
    const float* bq = (const float*)d_in[4];
    const float* Wk = (const float*)d_in[5];
    const float* bk = (const float*)d_in[6];
    const float* Wv = (const float*)d_in[7];
    const float* bv = (const float*)d_in[8];
    const float* Wo = (const float*)d_in[9];
    const float* bo = (const float*)d_in[10];
    float* out = (float*)d_out;

    float* qp;
    __nv_bfloat16 *kh, *kl, *vth, *vtl, *wh, *wl;
    float* attn;
    cudaGetSymbolAddress((void**)&qp,  g_q);
    cudaGetSymbolAddress((void**)&kh,  g_kh);
    cudaGetSymbolAddress((void**)&kl,  g_kl);
    cudaGetSymbolAddress((void**)&vth, g_vth);
    cudaGetSymbolAddress((void**)&vtl, g_vtl);
    cudaGetSymbolAddress((void**)&wh,  g_wh);
    cudaGetSymbolAddress((void**)&wl,  g_wl);
    if ((long long)out_size >= BSD_LL + ATTN_LL) {
        attn = out + BSD_LL;                 // tuple output: (out, attn)
    } else {
        cudaGetSymbolAddress((void**)&attn, g_attn_fallback);
    }
    float* ctx = qp;  // reuse g_q after logits are done

    const int WSZ = 1024 * 1024;
    // dynamic smem: 2 stages * (A hi/lo + B hi/lo), SK=40
    const int SM128 = 2 * (2 * 128 * 40 * 2 + 2 * 128 * 40 * 2);  // 81920
    const int SM64  = 2 * (2 * 128 * 40 * 2 + 2 * 64  * 40 * 2);  // 61440
    cudaFuncSetAttribute(gemm_mma<128,0>, cudaFuncAttributeMaxDynamicSharedMemorySize, SM128);
    cudaFuncSetAttribute(gemm_mma<128,1>, cudaFuncAttributeMaxDynamicSharedMemorySize, SM128);
    cudaFuncSetAttribute(gemm_mma<128,2>, cudaFuncAttributeMaxDynamicSharedMemorySize, SM128);
    cudaFuncSetAttribute(gemm_mma<64,0>,  cudaFuncAttributeMaxDynamicSharedMemorySize, SM64);

    const float inv_sqrt_dk = 0.125f; // 1/sqrt(64)

    // 0) Split weights to bf16 hi/lo
    split_f32<<<WSZ / 4 / 256, 256>>>(Wq, wh + 0 * WSZ, wl + 0 * WSZ, WSZ / 4);
    split_f32<<<WSZ / 4 / 256, 256>>>(Wk, wh + 1 * WSZ, wl + 1 * WSZ, WSZ / 4);
    split_f32<<<WSZ / 4 / 256, 256>>>(Wv, wh + 2 * WSZ, wl + 2 * WSZ, WSZ / 4);
    split_f32<<<WSZ / 4 / 256, 256>>>(Wo, wh + 3 * WSZ, wl + 3 * WSZ, WSZ / 4);

    // 1) Projections: [8192,1024] = X @ W^T + b
    {
        dim3 grid(D_ / 128, (int)(BS_LL / 128), 1);
        gemm_mma<128,0><<<grid, 256, SM128>>>(
            q, wh + 0 * WSZ, wl + 0 * WSZ, bq, qp, nullptr, nullptr,
            D_, D_, D_, D_, 0,0,0,0,0,0, 1, 1.0f);
        gemm_mma<128,1><<<grid, 256, SM128>>>(
            k, wh + 1 * WSZ, wl + 1 * WSZ, bk, nullptr, kh, kl,
            D_, D_, D_, D_, 0,0,0,0,0,0, 1, 1.0f);
        gemm_mma<128,2><<<grid, 256, SM128>>>(
            v, wh + 2 * WSZ, wl + 2 * WSZ, bv, nullptr, vth, vtl,
            D_, D_, D_, D_, 0,0,0,0,0,0, 1, 1.0f);
    }

    // 2) Logits: attn[b,h,i,j] = scale * dot(Qp[b,i,h*64:], Kh/l[b,j,h*64:])
    {
        dim3 grid(S_ / 128, S_ / 128, B_ * H_);
        gemm_mma<128,0><<<grid, 256, SM128>>>(
            qp, kh, kl, nullptr, attn, nullptr, nullptr,
            DK_, D_, D_, S_,
            (long long)S_ * D_, DK_,
            (long long)S_ * D_, DK_,
            (long long)H_ * S_ * S_, (long long)S_ * S_,
            H_, inv_sqrt_dk);
    }

    // 3) Softmax over last dim, in place
    softmax_rows2048<<<(unsigned)(B_ * H_ * S_), 256>>>(attn);

    // 4) Ctx: ctx[b,s,h*64+d] = sum_j attn[b,h,s,j] * Vt[b,h,d,j]
    {
        dim3 grid(1, S_ / 128, B_ * H_);
        gemm_mma<64,0><<<grid, 256, SM64>>>(
            attn, vth, vtl, nullptr, ctx, nullptr, nullptr,
            S_, S_, S_, D_,
            (long long)H_ * S_ * S_, (long long)S_ * S_,
            (long long)H_ * DK_ * S_, (long long)DK_ * S_,
            (long long)S_ * D_, (long long)DK_,
            H_, 1.0f);
    }

    // 5) Output projection: out = ctx @ Wo^T + bo
    {
        dim3 grid(D_ / 128, (int)(BS_LL / 128), 1);
        gemm_mma<128,0><<<grid, 256, SM128>>>(
            ctx, wh + 3 * WSZ, wl + 3 * WSZ, bo, out, nullptr, nullptr,
            D_, D_, D_, D_, 0,0,0,0,0,0, 1, 1.0f);
    }
}

// round 14
// speedup vs baseline: 1.0011x; 1.0011x over previous
#include <cuda_runtime.h>
#include <cuda_bf16.h>
#include <cstdint>

// Problem constants
#define B_  4
#define S_  2048
#define D_  1024
#define H_  16
#define DK_ 64

static const long long BS_LL   = (long long)B_ * S_;           // 8192
static const long long BSD_LL  = (long long)B_ * S_ * D_;      // 8388608
static const long long ATTN_LL = (long long)B_ * H_ * S_ * S_; // 268435456

// Scratch (allocation-free rule: __device__ globals)
__device__ float          g_q[(size_t)BSD_LL];    // Qp fp32; reused as Ctx fp32
__device__ __nv_bfloat16  g_kh[(size_t)BSD_LL], g_kl[(size_t)BSD_LL];   // Kp hi/lo
__device__ __nv_bfloat16  g_vth[(size_t)BSD_LL], g_vtl[(size_t)BSD_LL]; // Vt hi/lo [B][H][DK][S]
__device__ __nv_bfloat16  g_wh[4u * 1024u * 1024u], g_wl[4u * 1024u * 1024u];
__device__ float          g_attn_fallback[(size_t)ATTN_LL];

__device__ __forceinline__ uint32_t smem_u32(const void* p) {
    uint32_t a;
    asm("{ .reg .u64 t; cvta.to.shared.u64 t, %1; cvt.u32.u64 %0, t; }" : "=r"(a) : "l"(p));
    return a;
}
__device__ __forceinline__ void ldmx4(uint32_t* r, uint32_t addr) {
    asm volatile("ldmatrix.sync.aligned.m8n8.x4.shared.b16 {%0,%1,%2,%3}, [%4];"
                 : "=r"(r[0]), "=r"(r[1]), "=r"(r[2]), "=r"(r[3]) : "r"(addr));
}
__device__ __forceinline__ void ldmx2(uint32_t* r, uint32_t addr) {
    asm volatile("ldmatrix.sync.aligned.m8n8.x2.shared.b16 {%0,%1}, [%2];"
                 : "=r"(r[0]), "=r"(r[1]) : "r"(addr));
}
__device__ __forceinline__ void mma16816(float* c, const uint32_t* a, const uint32_t* b) {
    asm volatile(
        "mma.sync.aligned.m16n8k16.row.col.f32.bf16.bf16.f32 "
        "{%0,%1,%2,%3}, {%4,%5,%6,%7}, {%8,%9}, {%0,%1,%2,%3};"
        : "+f"(c[0]), "+f"(c[1]), "+f"(c[2]), "+f"(c[3])
        : "r"(a[0]), "r"(a[1]), "r"(a[2]), "r"(a[3]), "r"(b[0]), "r"(b[1]));
}
__device__ __forceinline__ void sts64(uint32_t addr, uint2 v) {
    asm volatile("st.shared.v2.b32 [%0], {%1, %2};" :: "r"(addr), "r"(v.x), "r"(v.y) : "memory");
}

// Split a float4 into packed bf16 hi (truncation, exact) and lo (remainder).
__device__ __forceinline__ void split4(const float4& v, uint2& hi, uint2& lo) {
    uint32_t ux = __float_as_uint(v.x), uy = __float_as_uint(v.y);
    uint32_t uz = __float_as_uint(v.z), uw = __float_as_uint(v.w);
    hi.x = (ux >> 16) | (uy & 0xFFFF0000u);
    hi.y = (uz >> 16) | (uw & 0xFFFF0000u);
    float lx = v.x - __uint_as_float(ux & 0xFFFF0000u);
    float ly = v.y - __uint_as_float(uy & 0xFFFF0000u);
    float lz = v.z - __uint_as_float(uz & 0xFFFF0000u);
    float lw = v.w - __uint_as_float(uw & 0xFFFF0000u);
    __nv_bfloat162 l0 = __floats2bfloat162_rn(lx, ly);
    __nv_bfloat162 l1 = __floats2bfloat162_rn(lz, lw);
    lo.x = *reinterpret_cast<uint32_t*>(&l0);
    lo.y = *reinterpret_cast<uint32_t*>(&l1);
}
// Pack hi bf16 (truncation) of two floats into one u32 (low half = first elem).
__device__ __forceinline__ uint32_t pack_hi(float2 v) {
    return (__float_as_uint(v.x) >> 16) | (__float_as_uint(v.y) & 0xFFFF0000u);
}
__device__ __forceinline__ uint32_t pack_lo(float2 v) {
    float hx = __uint_as_float(__float_as_uint(v.x) & 0xFFFF0000u);
    float hy = __uint_as_float(__float_as_uint(v.y) & 0xFFFF0000u);
    __nv_bfloat162 l = __floats2bfloat162_rn(v.x - hx, v.y - hy);
    return *reinterpret_cast<uint32_t*>(&l);
}

// fp32 -> bf16 hi/lo split (vectorized), for weights
__global__ __launch_bounds__(256) void split_f32(
    const float* __restrict__ src, __nv_bfloat16* __restrict__ dh,
    __nv_bfloat16* __restrict__ dl, int n4)
{
    int i = blockIdx.x * 256 + threadIdx.x;
    if (i >= n4) return;
    float4 v = reinterpret_cast<const float4*>(src)[i];
    uint2 h, l;
    split4(v, h, l);
    reinterpret_cast<uint2*>(dh)[i] = h;
    reinterpret_cast<uint2*>(dl)[i] = l;
}

// ---------------------------------------------------------------------------
// bf16-split GEMM: C[m,n] = scale * sum_k A[m,k]*B[n,k] (+ bias[n])
//  A fp32 (split in-loop, R6-verified path), B pre-split bf16 hi/lo.
//  2-stage smem double buffer, 1 sync/iter, ldmatrix everywhere.
//  EPI: 0 = fp32 C; 1 = bf16 hi/lo Ch/Cl; 2 = bf16 hi/lo transposed per-head.
// ---------------------------------------------------------------------------
template <int BN, int EPI>
__global__ __launch_bounds__(256) void gemm_mma(
    const float* __restrict__ A,
    const __nv_bfloat16* __restrict__ Bh, const __nv_bfloat16* __restrict__ Bl,
    const float* __restrict__ bias,
    float* __restrict__ C, __nv_bfloat16* __restrict__ Ch, __nv_bfloat16* __restrict__ Cl,
    int K, int lda, int ldb, int ldc,
    long long sAb, long long sAh, long long sBb, long long sBhh,
    long long sCb, long long sChh, int Hdim, float scale)
{
    constexpr int BM = 128, BK = 32;
    constexpr int SK = 40;                       // smem row stride in halves
    constexpr int NBB = BN / 64;                 // B uint4 loads per thread per array
    constexpr int WGM = (BN == 128) ? 2 : 4;
    constexpr int WGN = (BN == 128) ? 4 : 2;
    constexpr int WM = BM / WGM, WN = BN / WGN;
    constexpr int MF = WM / 16, NF = WN / 8;
    constexpr uint32_t OFF_AL = BM * SK * 2;
    constexpr uint32_t OFF_BH = 2u * BM * SK * 2;
    constexpr uint32_t OFF_BL = OFF_BH + BN * SK * 2;
    constexpr uint32_t STAGE  = OFF_BL + BN * SK * 2;

    extern __shared__ char sm_raw[];
    const uint32_t sbase = smem_u32(sm_raw);

    const int bz = blockIdx.z;
    const int bi = bz / Hdim, hz = bz % Hdim;
    A  += (long long)bi * sAb + (long long)hz * sAh;
    Bh += (long long)bi * sBb + (long long)hz * sBhh;
    Bl += (long long)bi * sBb + (long long)hz * sBhh;
    if (EPI == 0) C += (long long)bi * sCb + (long long)hz * sChh;

    const int tid = threadIdx.x;
    const int wid = tid >> 5, lane = tid & 31;
    const int wm = (BN == 128) ? (wid >> 2) : (wid >> 1);
    const int wn = (BN == 128) ? (wid & 3) : (wid & 1);
    const int row0 = blockIdx.y * BM;
    const int col0 = blockIdx.x * BN;

    float acc[MF][NF][4];
#pragma unroll
    for (int i = 0; i < MF; i++)
#pragma unroll
        for (int j = 0; j < NF; j++)
#pragma unroll
            for (int c = 0; c < 4; c++) acc[i][j][c] = 0.0f;

    // ldmatrix per-thread row assignments (R6-verified)
    const int a_row = wm * WM + (lane & 15);        // + mf*16
    const int a_kof = 8 * (lane >> 4);
    const int b_row = wn * WN + (lane & 7);         // + nf*8
    const int b_kof = 8 * ((lane >> 3) & 1);

    // staging assignments
    const int sa_r = tid >> 3, sa_c = (tid & 7) * 4;   // A: +j*32 rows, col in elems
    const int sb_r = tid >> 2, sb_c = (tid & 3) * 8;   // B: +j*64 rows, col in halves

    float4 a4[4];
    uint4  bh4[NBB], bl4[NBB];

#define LOAD_A(KT)                                                              \
    _Pragma("unroll")                                                           \
    for (int j = 0; j < 4; j++) {                                               \
        a4[j] = *reinterpret_cast<const float4*>(                               \
            A + (long long)(row0 + sa_r + j * 32) * lda + (KT) + sa_c);         \
    }
#define LOAD_B(KT)                                                              \
    _Pragma("unroll")                                                           \
    for (int j = 0; j < NBB; j++) {                                             \
        bh4[j] = *reinterpret_cast<const uint4*>(                               \
            Bh + (long long)(col0 + sb_r + j * 64) * ldb + (KT) + sb_c);        \
        bl4[j] = *reinterpret_cast<const uint4*>(                               \
            Bl + (long long)(col0 + sb_r + j * 64) * ldb + (KT) + sb_c);        \
    }
#define STORE_STAGE(S)                                                          \
    {                                                                           \
        const uint32_t sb = sbase + (uint32_t)(S) * STAGE;                      \
        _Pragma("unroll")                                                       \
        for (int j = 0; j < 4; j++) {                                           \
            uint2 h, l; split4(a4[j], h, l);                                    \
            uint32_t o = ((sa_r + j * 32) * SK + sa_c) * 2;                     \
            sts64(sb + o, h);                                                   \
            sts64(sb + OFF_AL + o, l);                                          \
        }                                                                       \
        _Pragma("unroll")                                                       \
        for (int j = 0; j < NBB; j++) {                                         \
            uint32_t o = ((sb_r + j * 64) * SK + sb_c) * 2;                     \
            sts64(sb + OFF_BH + o, make_uint2(bh4[j].x, bh4[j].y));             \
            sts64(sb + OFF_BH + o + 8, make_uint2(bh4[j].z, bh4[j].w));         \
            sts64(sb + OFF_BL + o, make_uint2(bl4[j].x, bl4[j].y));             \
            sts64(sb + OFF_BL + o + 8, make_uint2(bl4[j].z, bl4[j].w));         \
        }                                                                       \
    }

    const int nIter = K / BK;

    // Preamble: tile 0 -> stage 0; tile 1 -> regs
    LOAD_A(0); LOAD_B(0);
    STORE_STAGE(0);
    if (nIter > 1) { LOAD_A(BK); LOAD_B(BK); }
    __syncthreads();

    for (int i = 0; i < nIter; i++) {
        const int s = i & 1;
        if (i + 1 < nIter) STORE_STAGE(s ^ 1);           // STS drains during MMA
        if (i + 2 < nIter) { LOAD_A((i + 2) * BK); LOAD_B((i + 2) * BK); }

        const uint32_t sb = sbase + (uint32_t)s * STAGE;
#pragma unroll
        for (int ks = 0; ks < 2; ks++) {
            const int k16 = ks * 16;
            uint32_t bhf[NF][2], blf[NF][2];
#pragma unroll
            for (int nf = 0; nf < NF; nf++) {
                uint32_t off = ((b_row + nf * 8) * SK + k16 + b_kof) * 2;
                ldmx2(bhf[nf], sb + OFF_BH + off);
                ldmx2(blf[nf], sb + OFF_BL + off);
            }
#pragma unroll
            for (int mf = 0; mf < MF; mf++) {
                uint32_t ah[4], al[4];
                uint32_t off = ((a_row + mf * 16) * SK + k16 + a_kof) * 2;
                ldmx4(ah, sb + off);
                ldmx4(al, sb + OFF_AL + off);
#pragma unroll
                for (int nf = 0; nf < NF; nf++) {
                    mma16816(acc[mf][nf], ah, bhf[nf]);   // hi*hi
                    mma16816(acc[mf][nf], al, bhf[nf]);   // lo*hi
                    mma16816(acc[mf][nf], ah, blf[nf]);   // hi*lo
                }
            }
        }
        __syncthreads();
    }
#undef LOAD_A
#undef LOAD_B
#undef STORE_STAGE

    // Epilogue
#pragma unroll
    for (int mf = 0; mf < MF; mf++) {
#pragma unroll
        for (int nf = 0; nf < NF; nf++) {
            const int rg = row0 + wm * WM + mf * 16 + (lane >> 2);
            const int cg = col0 + wn * WN + nf * 8 + 2 * (lane & 3);
            float2 v0, v1;
            v0.x = acc[mf][nf][0] * scale; v0.y = acc[mf][nf][1] * scale;
            v1.x = acc[mf][nf][2] * scale; v1.y = acc[mf][nf][3] * scale;
            if (bias) {
                float bx = __ldg(bias + cg), by = __ldg(bias + cg + 1);
                v0.x += bx; v0.y += by; v1.x += bx; v1.y += by;
            }
            if (EPI == 0) {
                *reinterpret_cast<float2*>(C + (long long)rg * ldc + cg) = v0;
                *reinterpret_cast<float2*>(C + (long long)(rg + 8) * ldc + cg) = v1;
            } else if (EPI == 1) {
                *reinterpret_cast<uint32_t*>(Ch + (long long)rg * ldc + cg) = pack_hi(v0);
                *reinterpret_cast<uint32_t*>(Cl + (long long)rg * ldc + cg) = pack_lo(v0);
                *reinterpret_cast<uint32_t*>(Ch + (long long)(rg + 8) * ldc + cg) = pack_hi(v1);
                *reinterpret_cast<uint32_t*>(Cl + (long long)(rg + 8) * ldc + cg) = pack_lo(v1);
            } else {
                // transposed per-head: [((b*H + h)*DK + d)*S + s]   (R6-verified indexing)
                float vv[4] = {v0.x, v0.y, v1.x, v1.y};
#pragma unroll
                for (int e = 0; e < 4; e++) {
                    const int r = rg + (e >> 1) * 8;
                    const int n = cg + (e & 1);
                    const int b = r >> 11, ss = r & 2047;
                    const long long idx =
                        (((long long)(b * H_ + (n >> 6)) * DK_ + (n & 63)) << 11) + ss;
                    float x = vv[e];
                    uint32_t ux = __float_as_uint(x);
                    Ch[idx] = __ushort_as_bfloat16((unsigned short)(ux >> 16));
                    Cl[idx] = __float2bfloat16(x - __uint_as_float(ux & 0xFFFF0000u));
                }
            }
        }
    }
}

// ---------------------------------------------------------------------------
// Row softmax, row length 2048, register-resident.
// ---------------------------------------------------------------------------
__global__ __launch_bounds__(256) void softmax_rows2048(float* __restrict__ att)
{
    float4* p4 = reinterpret_cast<float4*>(att + (long long)blockIdx.x * 2048);
    const int tid = threadIdx.x;
    __shared__ float red[32];

    float4 v0 = p4[tid];
    float4 v1 = p4[tid + 256];

    float m = fmaxf(fmaxf(fmaxf(v0.x, v0.y), fmaxf(v0.z, v0.w)),
                    fmaxf(fmaxf(v1.x, v1.y), fmaxf(v1.z, v1.w)));
#pragma unroll
    for (int o = 16; o > 0; o >>= 1) m = fmaxf(m, __shfl_xor_sync(0xffffffffu, m, o));
    if ((tid & 31) == 0) red[tid >> 5] = m;
    __syncthreads();
    if (tid < 32) {
        float t = red[tid & 7];
#pragma unroll
        for (int o = 4; o > 0; o >>= 1) t = fmaxf(t, __shfl_xor_sync(0xffffffffu, t, o));
        red[tid & 7] = t;
    }
    __syncthreads();
    m = red[0];

    v0.x = __expf(v0.x - m); v0.y = __expf(v0.y - m);
    v0.z = __expf(v0.z - m); v0.w = __expf(v0.w - m);
    v1.x = __expf(v1.x - m); v1.y = __expf(v1.y - m);
    v1.z = __expf(v1.z - m); v1.w = __expf(v1.w - m);
    float s = v0.x + v0.y + v0.z + v0.w + v1.x + v1.y + v1.z + v1.w;
#pragma unroll
    for (int o = 16; o > 0; o >>= 1) s += __shfl_xor_sync(0xffffffffu, s, o);
    __syncthreads();
    if ((tid & 31) == 0) red[tid >> 5] = s;
    __syncthreads();
    if (tid < 32) {
        float t = red[tid & 7];
#pragma unroll
        for (int o = 4; o > 0; o >>= 1) t += __shfl_xor_sync(0xffffffffu, t, o);
        red[tid & 7] = t;
    }
    __syncthreads();
    const float inv = 1.0f / red[0];

    v0.x *= inv; v0.y *= inv; v0.z *= inv; v0.w *= inv;
    v1.x *= inv; v1.y *= inv; v1.z *= inv; v1.w *= inv;
    p4[tid] = v0;
    p4[tid + 256] = v1;
}

extern "C" void kernel_launch(void* const* d_in, const int* in_sizes, int n_in,
                              void* d_out, int out_size)
{
    const float* q  = (const float*)d_in[0];
    const float* k  = (const float*)d_in[1];
    const float* v  = (const float*)d_in[2];
    const float* Wq = (const float*)d_in[3];
    const float* bq = (const float*)d_in[4];
    const float* Wk = (const float*)d_in[5];
    const float* bk = (const float*)d_in[6];
    const float* Wv = (const float*)d_in[7];
    const float* bv = (const float*)d_in[8];
    const float* Wo = (const float*)d_in[9];
    const float* bo = (const float*)d_in[10];
    float* out = (float*)d_out;

    float* qp;
    __nv_bfloat16 *kh, *kl, *vth, *vtl, *wh, *wl;
    float* attn;
    cudaGetSymbolAddress((void**)&qp,  g_q);
    cudaGetSymbolAddress((void**)&kh,  g_kh);
    cudaGetSymbolAddress((void**)&kl,  g_kl);
    cudaGetSymbolAddress((void**)&vth, g_vth);
    cudaGetSymbolAddress((void**)&vtl, g_vtl);
    cudaGetSymbolAddress((void**)&wh,  g_wh);
    cudaGetSymbolAddress((void**)&wl,  g_wl);
    if ((long long)out_size >= BSD_LL + ATTN_LL) {
        attn = out + BSD_LL;                 // tuple output: (out, attn)
    } else {
        cudaGetSymbolAddress((void**)&attn, g_attn_fallback);
    }
    float* ctx = qp;  // reuse g_q after logits are done

    const int WSZ = 1024 * 1024;
    // dynamic smem: 2 stages * (A hi/lo + B hi/lo), SK=40
    const int SM128 = 2 * (2 * 128 * 40 * 2 + 2 * 128 * 40 * 2);  // 81920
    const int SM64  = 2 * (2 * 128 * 40 * 2 + 2 * 64  * 40 * 2);  // 61440
    cudaFuncSetAttribute(gemm_mma<128,0>, cudaFuncAttributeMaxDynamicSharedMemorySize, SM128);
    cudaFuncSetAttribute(gemm_mma<128,1>, cudaFuncAttributeMaxDynamicSharedMemorySize, SM128);
    cudaFuncSetAttribute(gemm_mma<128,2>, cudaFuncAttributeMaxDynamicSharedMemorySize, SM128);
    cudaFuncSetAttribute(gemm_mma<64,0>,  cudaFuncAttributeMaxDynamicSharedMemorySize, SM64);

    const float inv_sqrt_dk = 0.125f; // 1/sqrt(64)

    // 0) Split weights to bf16 hi/lo
    split_f32<<<WSZ / 4 / 256, 256>>>(Wq, wh + 0 * WSZ, wl + 0 * WSZ, WSZ / 4);
    split_f32<<<WSZ / 4 / 256, 256>>>(Wk, wh + 1 * WSZ, wl + 1 * WSZ, WSZ / 4);
    split_f32<<<WSZ / 4 / 256, 256>>>(Wv, wh + 2 * WSZ, wl + 2 * WSZ, WSZ / 4);
    split_f32<<<WSZ / 4 / 256, 256>>>(Wo, wh + 3 * WSZ, wl + 3 * WSZ, WSZ / 4);

    // 1) Projections: [8192,1024] = X @ W^T + b
    {
        dim3 grid(D_ / 128, (int)(BS_LL / 128), 1);
        gemm_mma<128,0><<<grid, 256, SM128>>>(
            q, wh + 0 * WSZ, wl + 0 * WSZ, bq, qp, nullptr, nullptr,
            D_, D_, D_, D_, 0,0,0,0,0,0, 1, 1.0f);
        gemm_mma<128,1><<<grid, 256, SM128>>>(
            k, wh + 1 * WSZ, wl + 1 * WSZ, bk, nullptr, kh, kl,
            D_, D_, D_, D_, 0,0,0,0,0,0, 1, 1.0f);
        gemm_mma<128,2><<<grid, 256, SM128>>>(
            v, wh + 2 * WSZ, wl + 2 * WSZ, bv, nullptr, vth, vtl,
            D_, D_, D_, D_, 0,0,0,0,0,0, 1, 1.0f);
    }

    // 2) Logits: attn[b,h,i,j] = scale * dot(Qp[b,i,h*64:], Kh/l[b,j,h*64:])
    {
        dim3 grid(S_ / 128, S_ / 128, B_ * H_);
        gemm_mma<128,0><<<grid, 256, SM128>>>(
            qp, kh, kl, nullptr, attn, nullptr, nullptr,
            DK_, D_, D_, S_,
            (long long)S_ * D_, DK_,
            (long long)S_ * D_, DK_,
            (long long)H_ * S_ * S_, (long long)S_ * S_,
            H_, inv_sqrt_dk);
    }

    // 3) Softmax over last dim, in place
    softmax_rows2048<<<(unsigned)(B_ * H_ * S_), 256>>>(attn);

    // 4) Ctx: ctx[b,s,h*64+d] = sum_j attn[b,h,s,j] * Vt[b,h,d,j]
    {
        dim3 grid(1, S_ / 128, B_ * H_);
        gemm_mma<64,0><<<grid, 256, SM64>>>(
            attn, vth, vtl, nullptr, ctx, nullptr, nullptr,
            S_, S_, S_, D_,
            (long long)H_ * S_ * S_, (long long)S_ * S_,
            (long long)H_ * DK_ * S_, (long long)DK_ * S_,
            (long long)S_ * D_, (long long)DK_,
            H_, 1.0f);
    }

    // 5) Output projection: out = ctx @ Wo^T + bo
    {
        dim3 grid(D_ / 128, (int)(BS_LL / 128), 1);
        gemm_mma<128,0><<<grid, 256, SM128>>>(
            ctx, wh + 3 * WSZ, wl + 3 * WSZ, bo, out, nullptr, nullptr,
            D_, D_, D_, D_, 0,0,0,0,0,0, 1, 1.0f);
    }
}

// round 15
// speedup vs baseline: 1.0018x; 1.0008x over previous
#include <cuda_runtime.h>
#include <cuda_bf16.h>
#include <cstdint>

// Problem constants
#define B_  4
#define S_  2048
#define D_  1024
#define H_  16
#define DK_ 64

static const long long BS_LL   = (long long)B_ * S_;           // 8192
static const long long BSD_LL  = (long long)B_ * S_ * D_;      // 8388608
static const long long ATTN_LL = (long long)B_ * H_ * S_ * S_; // 268435456

// Scratch (allocation-free rule: __device__ globals)
__device__ float          g_q[(size_t)BSD_LL];    // Qp fp32; reused as Ctx fp32
__device__ __nv_bfloat16  g_kh[(size_t)BSD_LL], g_kl[(size_t)BSD_LL];   // Kp hi/lo
__device__ __nv_bfloat16  g_vth[(size_t)BSD_LL], g_vtl[(size_t)BSD_LL]; // Vt hi/lo [B][H][DK][S]
__device__ __nv_bfloat16  g_wh[4u * 1024u * 1024u], g_wl[4u * 1024u * 1024u];
__device__ float          g_attn_fallback[(size_t)ATTN_LL];

__device__ __forceinline__ uint32_t smem_u32(const void* p) {
    uint32_t a;
    asm("{ .reg .u64 t; cvta.to.shared.u64 t, %1; cvt.u32.u64 %0, t; }" : "=r"(a) : "l"(p));
    return a;
}
__device__ __forceinline__ void ldmx4(uint32_t* r, uint32_t addr) {
    asm volatile("ldmatrix.sync.aligned.m8n8.x4.shared.b16 {%0,%1,%2,%3}, [%4];"
                 : "=r"(r[0]), "=r"(r[1]), "=r"(r[2]), "=r"(r[3]) : "r"(addr));
}
__device__ __forceinline__ void ldmx2(uint32_t* r, uint32_t addr) {
    asm volatile("ldmatrix.sync.aligned.m8n8.x2.shared.b16 {%0,%1}, [%2];"
                 : "=r"(r[0]), "=r"(r[1]) : "r"(addr));
}
__device__ __forceinline__ void mma16816(float* c, const uint32_t* a, const uint32_t* b) {
    asm volatile(
        "mma.sync.aligned.m16n8k16.row.col.f32.bf16.bf16.f32 "
        "{%0,%1,%2,%3}, {%4,%5,%6,%7}, {%8,%9}, {%0,%1,%2,%3};"
        : "+f"(c[0]), "+f"(c[1]), "+f"(c[2]), "+f"(c[3])
        : "r"(a[0]), "r"(a[1]), "r"(a[2]), "r"(a[3]), "r"(b[0]), "r"(b[1]));
}
__device__ __forceinline__ void sts64(uint32_t addr, uint2 v) {
    asm volatile("st.shared.v2.b32 [%0], {%1, %2};" :: "r"(addr), "r"(v.x), "r"(v.y) : "memory");
}

// Split a float4 into packed bf16 hi (truncation, exact) and lo (remainder).
__device__ __forceinline__ void split4(const float4& v, uint2& hi, uint2& lo) {
    uint32_t ux = __float_as_uint(v.x), uy = __float_as_uint(v.y);
    uint32_t uz = __float_as_uint(v.z), uw = __float_as_uint(v.w);
    hi.x = (ux >> 16) | (uy & 0xFFFF0000u);
    hi.y = (uz >> 16) | (uw & 0xFFFF0000u);
    float lx = v.x - __uint_as_float(ux & 0xFFFF0000u);
    float ly = v.y - __uint_as_float(uy & 0xFFFF0000u);
    float lz = v.z - __uint_as_float(uz & 0xFFFF0000u);
    float lw = v.w - __uint_as_float(uw & 0xFFFF0000u);
    __nv_bfloat162 l0 = __floats2bfloat162_rn(lx, ly);
    __nv_bfloat162 l1 = __floats2bfloat162_rn(lz, lw);
    lo.x = *reinterpret_cast<uint32_t*>(&l0);
    lo.y = *reinterpret_cast<uint32_t*>(&l1);
}
// Pack hi bf16 (truncation) of two floats into one u32 (low half = first elem).
__device__ __forceinline__ uint32_t pack_hi(float2 v) {
    return (__float_as_uint(v.x) >> 16) | (__float_as_uint(v.y) & 0xFFFF0000u);
}
__device__ __forceinline__ uint32_t pack_lo(float2 v) {
    float hx = __uint_as_float(__float_as_uint(v.x) & 0xFFFF0000u);
    float hy = __uint_as_float(__float_as_uint(v.y) & 0xFFFF0000u);
    __nv_bfloat162 l = __floats2bfloat162_rn(v.x - hx, v.y - hy);
    return *reinterpret_cast<uint32_t*>(&l);
}

// fp32 -> bf16 hi/lo split (vectorized), for weights
__global__ __launch_bounds__(256) void split_f32(
    const float* __restrict__ src, __nv_bfloat16* __restrict__ dh,
    __nv_bfloat16* __restrict__ dl, int n4)
{
    int i = blockIdx.x * 256 + threadIdx.x;
    if (i >= n4) return;
    float4 v = reinterpret_cast<const float4*>(src)[i];
    uint2 h, l;
    split4(v, h, l);
    reinterpret_cast<uint2*>(dh)[i] = h;
    reinterpret_cast<uint2*>(dl)[i] = l;
}

// ---------------------------------------------------------------------------
// bf16-split GEMM: C[m,n] = scale * sum_k A[m,k]*B[n,k] (+ bias[n])
//  A fp32 (split in-loop, R6-verified path), B pre-split bf16 hi/lo.
//  2-stage smem double buffer, 1 sync/iter, ldmatrix everywhere.
//  EPI: 0 = fp32 C; 1 = bf16 hi/lo Ch/Cl; 2 = bf16 hi/lo transposed per-head.
// ---------------------------------------------------------------------------
template <int BN, int EPI>
__global__ __launch_bounds__(256) void gemm_mma(
    const float* __restrict__ A,
    const __nv_bfloat16* __restrict__ Bh, const __nv_bfloat16* __restrict__ Bl,
    const float* __restrict__ bias,
    float* __restrict__ C, __nv_bfloat16* __restrict__ Ch, __nv_bfloat16* __restrict__ Cl,
    int K, int lda, int ldb, int ldc,
    long long sAb, long long sAh, long long sBb, long long sBhh,
    long long sCb, long long sChh, int Hdim, float scale)
{
    constexpr int BM = 128, BK = 32;
    constexpr int SK = 40;                       // smem row stride in halves
    constexpr int NBB = BN / 64;                 // B uint4 loads per thread per array
    constexpr int WGM = (BN == 128) ? 2 : 4;
    constexpr int WGN = (BN == 128) ? 4 : 2;
    constexpr int WM = BM / WGM, WN = BN / WGN;
    constexpr int MF = WM / 16, NF = WN / 8;
    constexpr uint32_t OFF_AL = BM * SK * 2;
    constexpr uint32_t OFF_BH = 2u * BM * SK * 2;
    constexpr uint32_t OFF_BL = OFF_BH + BN * SK * 2;
    constexpr uint32_t STAGE  = OFF_BL + BN * SK * 2;

    extern __shared__ char sm_raw[];
    const uint32_t sbase = smem_u32(sm_raw);

    const int bz = blockIdx.z;
    const int bi = bz / Hdim, hz = bz % Hdim;
    A  += (long long)bi * sAb + (long long)hz * sAh;
    Bh += (long long)bi * sBb + (long long)hz * sBhh;
    Bl += (long long)bi * sBb + (long long)hz * sBhh;
    if (EPI == 0) C += (long long)bi * sCb + (long long)hz * sChh;

    const int tid = threadIdx.x;
    const int wid = tid >> 5, lane = tid & 31;
    const int wm = (BN == 128) ? (wid >> 2) : (wid >> 1);
    const int wn = (BN == 128) ? (wid & 3) : (wid & 1);
    const int row0 = blockIdx.y * BM;
    const int col0 = blockIdx.x * BN;

    float acc[MF][NF][4];
#pragma unroll
    for (int i = 0; i < MF; i++)
#pragma unroll
        for (int j = 0; j < NF; j++)
#pragma unroll
            for (int c = 0; c < 4; c++) acc[i][j][c] = 0.0f;

    // ldmatrix per-thread row assignments (R6-verified)
    const int a_row = wm * WM + (lane & 15);        // + mf*16
    const int a_kof = 8 * (lane >> 4);
    const int b_row = wn * WN + (lane & 7);         // + nf*8
    const int b_kof = 8 * ((lane >> 3) & 1);

    // staging assignments
    const int sa_r = tid >> 3, sa_c = (tid & 7) * 4;   // A: +j*32 rows, col in elems
    const int sb_r = tid >> 2, sb_c = (tid & 3) * 8;   // B: +j*64 rows, col in halves

    float4 a4[4];
    uint4  bh4[NBB], bl4[NBB];

#define LOAD_A(KT)                                                              \
    _Pragma("unroll")                                                           \
    for (int j = 0; j < 4; j++) {                                               \
        a4[j] = *reinterpret_cast<const float4*>(                               \
            A + (long long)(row0 + sa_r + j * 32) * lda + (KT) + sa_c);         \
    }
#define LOAD_B(KT)                                                              \
    _Pragma("unroll")                                                           \
    for (int j = 0; j < NBB; j++) {                                             \
        bh4[j] = *reinterpret_cast<const uint4*>(                               \
            Bh + (long long)(col0 + sb_r + j * 64) * ldb + (KT) + sb_c);        \
        bl4[j] = *reinterpret_cast<const uint4*>(                               \
            Bl + (long long)(col0 + sb_r + j * 64) * ldb + (KT) + sb_c);        \
    }
#define STORE_STAGE(S)                                                          \
    {                                                                           \
        const uint32_t sb = sbase + (uint32_t)(S) * STAGE;                      \
        _Pragma("unroll")                                                       \
        for (int j = 0; j < 4; j++) {                                           \
            uint2 h, l; split4(a4[j], h, l);                                    \
            uint32_t o = ((sa_r + j * 32) * SK + sa_c) * 2;                     \
            sts64(sb + o, h);                                                   \
            sts64(sb + OFF_AL + o, l);                                          \
        }                                                                       \
        _Pragma("unroll")                                                       \
        for (int j = 0; j < NBB; j++) {                                         \
            uint32_t o = ((sb_r + j * 64) * SK + sb_c) * 2;                     \
            sts64(sb + OFF_BH + o, make_uint2(bh4[j].x, bh4[j].y));             \
            sts64(sb + OFF_BH + o + 8, make_uint2(bh4[j].z, bh4[j].w));         \
            sts64(sb + OFF_BL + o, make_uint2(bl4[j].x, bl4[j].y));             \
            sts64(sb + OFF_BL + o + 8, make_uint2(bl4[j].z, bl4[j].w));         \
        }                                                                       \
    }

    const int nIter = K / BK;

    // Preamble: tile 0 -> stage 0; tile 1 -> regs
    LOAD_A(0); LOAD_B(0);
    STORE_STAGE(0);
    if (nIter > 1) { LOAD_A(BK); LOAD_B(BK); }
    __syncthreads();

    for (int i = 0; i < nIter; i++) {
        const int s = i & 1;
        if (i + 1 < nIter) STORE_STAGE(s ^ 1);           // STS drains during MMA
        if (i + 2 < nIter) { LOAD_A((i + 2) * BK); LOAD_B((i + 2) * BK); }

        const uint32_t sb = sbase + (uint32_t)s * STAGE;
#pragma unroll
        for (int ks = 0; ks < 2; ks++) {
            const int k16 = ks * 16;
            uint32_t bhf[NF][2], blf[NF][2];
#pragma unroll
            for (int nf = 0; nf < NF; nf++) {
                uint32_t off = ((b_row + nf * 8) * SK + k16 + b_kof) * 2;
                ldmx2(bhf[nf], sb + OFF_BH + off);
                ldmx2(blf[nf], sb + OFF_BL + off);
            }
#pragma unroll
            for (int mf = 0; mf < MF; mf++) {
                uint32_t ah[4], al[4];
                uint32_t off = ((a_row + mf * 16) * SK + k16 + a_kof) * 2;
                ldmx4(ah, sb + off);
                ldmx4(al, sb + OFF_AL + off);
#pragma unroll
                for (int nf = 0; nf < NF; nf++) {
                    mma16816(acc[mf][nf], ah, bhf[nf]);   // hi*hi
                    mma16816(acc[mf][nf], al, bhf[nf]);   // lo*hi
                    mma16816(acc[mf][nf], ah, blf[nf]);   // hi*lo
                }
            }
        }
        __syncthreads();
    }
#undef LOAD_A
#undef LOAD_B
#undef STORE_STAGE

    // Epilogue
#pragma unroll
    for (int mf = 0; mf < MF; mf++) {
#pragma unroll
        for (int nf = 0; nf < NF; nf++) {
            const int rg = row0 + wm * WM + mf * 16 + (lane >> 2);
            const int cg = col0 + wn * WN + nf * 8 + 2 * (lane & 3);
            float2 v0, v1;
            v0.x = acc[mf][nf][0] * scale; v0.y = acc[mf][nf][1] * scale;
            v1.x = acc[mf][nf][2] * scale; v1.y = acc[mf][nf][3] * scale;
            if (bias) {
                float bx = __ldg(bias + cg), by = __ldg(bias + cg + 1);
                v0.x += bx; v0.y += by; v1.x += bx; v1.y += by;
            }
            if (EPI == 0) {
                *reinterpret_cast<float2*>(C + (long long)rg * ldc + cg) = v0;
                *reinterpret_cast<float2*>(C + (long long)(rg + 8) * ldc + cg) = v1;
            } else if (EPI == 1) {
                *reinterpret_cast<uint32_t*>(Ch + (long long)rg * ldc + cg) = pack_hi(v0);
                *reinterpret_cast<uint32_t*>(Cl + (long long)rg * ldc + cg) = pack_lo(v0);
                *reinterpret_cast<uint32_t*>(Ch + (long long)(rg + 8) * ldc + cg) = pack_hi(v1);
                *reinterpret_cast<uint32_t*>(Cl + (long long)(rg + 8) * ldc + cg) = pack_lo(v1);
            } else {
                // transposed per-head: [((b*H + h)*DK + d)*S + s]   (R6-verified indexing)
                float vv[4] = {v0.x, v0.y, v1.x, v1.y};
#pragma unroll
                for (int e = 0; e < 4; e++) {
                    const int r = rg + (e >> 1) * 8;
                    const int n = cg + (e & 1);
                    const int b = r >> 11, ss = r & 2047;
                    const long long idx =
                        (((long long)(b * H_ + (n >> 6)) * DK_ + (n & 63)) << 11) + ss;
                    float x = vv[e];
                    uint32_t ux = __float_as_uint(x);
                    Ch[idx] = __ushort_as_bfloat16((unsigned short)(ux >> 16));
                    Cl[idx] = __float2bfloat16(x - __uint_as_float(ux & 0xFFFF0000u));
                }
            }
        }
    }
}

// ---------------------------------------------------------------------------
// Row softmax, row length 2048, register-resident.
// ---------------------------------------------------------------------------
__global__ __launch_bounds__(256) void softmax_rows2048(float* __restrict__ att)
{
    float4* p4 = reinterpret_cast<float4*>(att + (long long)blockIdx.x * 2048);
    const int tid = threadIdx.x;
    __shared__ float red[32];

    float4 v0 = p4[tid];
    float4 v1 = p4[tid + 256];

    float m = fmaxf(fmaxf(fmaxf(v0.x, v0.y), fmaxf(v0.z, v0.w)),
                    fmaxf(fmaxf(v1.x, v1.y), fmaxf(v1.z, v1.w)));
#pragma unroll
    for (int o = 16; o > 0; o >>= 1) m = fmaxf(m, __shfl_xor_sync(0xffffffffu, m, o));
    if ((tid & 31) == 0) red[tid >> 5] = m;
    __syncthreads();
    if (tid < 32) {
        float t = red[tid & 7];
#pragma unroll
        for (int o = 4; o > 0; o >>= 1) t = fmaxf(t, __shfl_xor_sync(0xffffffffu, t, o));
        red[tid & 7] = t;
    }
    __syncthreads();
    m = red[0];

    v0.x = __expf(v0.x - m); v0.y = __expf(v0.y - m);
    v0.z = __expf(v0.z - m); v0.w = __expf(v0.w - m);
    v1.x = __expf(v1.x - m); v1.y = __expf(v1.y - m);
    v1.z = __expf(v1.z - m); v1.w = __expf(v1.w - m);
    float s = v0.x + v0.y + v0.z + v0.w + v1.x + v1.y + v1.z + v1.w;
#pragma unroll
    for (int o = 16; o > 0; o >>= 1) s += __shfl_xor_sync(0xffffffffu, s, o);
    __syncthreads();
    if ((tid & 31) == 0) red[tid >> 5] = s;
    __syncthreads();
    if (tid < 32) {
        float t = red[tid & 7];
#pragma unroll
        for (int o = 4; o > 0; o >>= 1) t += __shfl_xor_sync(0xffffffffu, t, o);
        red[tid & 7] = t;
    }
    __syncthreads();
    const float inv = 1.0f / red[0];

    v0.x *= inv; v0.y *= inv; v0.z *= inv; v0.w *= inv;
    v1.x *= inv; v1.y *= inv; v1.z *= inv; v1.w *= inv;
    p4[tid] = v0;
    p4[tid + 256] = v1;
}

extern "C" void kernel_launch(void* const* d_in, const int* in_sizes, int n_in,
                              void* d_out, int out_size)
{
    const float* q  = (const float*)d_in[0];
    const float* k  = (const float*)d_in[1];
    const float* v  = (const float*)d_in[2];
    const float* Wq = (const float*)d_in[3];
    const float* bq = (const float*)d_in[4];
    const float* Wk = (const float*)d_in[5];
    const float* bk = (const float*)d_in[6];
    const float* Wv = (const float*)d_in[7];
    const float* bv = (const float*)d_in[8];
    const float* Wo = (const float*)d_in[9];
    const float* bo = (const float*)d_in[10];
    float* out = (float*)d_out;

    float* qp;
    __nv_bfloat16 *kh, *kl, *vth, *vtl, *wh, *wl;
    float* attn;
    cudaGetSymbolAddress((void**)&qp,  g_q);
    cudaGetSymbolAddress((void**)&kh,  g_kh);
    cudaGetSymbolAddress((void**)&kl,  g_kl);
    cudaGetSymbolAddress((void**)&vth, g_vth);
    cudaGetSymbolAddress((void**)&vtl, g_vtl);
    cudaGetSymbolAddress((void**)&wh,  g_wh);
    cudaGetSymbolAddress((void**)&wl,  g_wl);
    if ((long long)out_size >= BSD_LL + ATTN_LL) {
        attn = out + BSD_LL;                 // tuple output: (out, attn)
    } else {
        cudaGetSymbolAddress((void**)&attn, g_attn_fallback);
    }
    float* ctx = qp;  // reuse g_q after logits are done

    const int WSZ = 1024 * 1024;
    // dynamic smem: 2 stages * (A hi/lo + B hi/lo), SK=40
    const int SM128 = 2 * (2 * 128 * 40 * 2 + 2 * 128 * 40 * 2);  // 81920
    const int SM64  = 2 * (2 * 128 * 40 * 2 + 2 * 64  * 40 * 2);  // 61440
    cudaFuncSetAttribute(gemm_mma<128,0>, cudaFuncAttributeMaxDynamicSharedMemorySize, SM128);
    cudaFuncSetAttribute(gemm_mma<128,1>, cudaFuncAttributeMaxDynamicSharedMemorySize, SM128);
    cudaFuncSetAttribute(gemm_mma<128,2>, cudaFuncAttributeMaxDynamicSharedMemorySize, SM128);
    cudaFuncSetAttribute(gemm_mma<64,0>,  cudaFuncAttributeMaxDynamicSharedMemorySize, SM64);

    const float inv_sqrt_dk = 0.125f; // 1/sqrt(64)

    // 0) Split weights to bf16 hi/lo
    split_f32<<<WSZ / 4 / 256, 256>>>(Wq, wh + 0 * WSZ, wl + 0 * WSZ, WSZ / 4);
    split_f32<<<WSZ / 4 / 256, 256>>>(Wk, wh + 1 * WSZ, wl + 1 * WSZ, WSZ / 4);
    split_f32<<<WSZ / 4 / 256, 256>>>(Wv, wh + 2 * WSZ, wl + 2 * WSZ, WSZ / 4);
    split_f32<<<WSZ / 4 / 256, 256>>>(Wo, wh + 3 * WSZ, wl + 3 * WSZ, WSZ / 4);

    // 1) Projections: [8192,1024] = X @ W^T + b
    {
        dim3 grid(D_ / 128, (int)(BS_LL / 128), 1);
        gemm_mma<128,0><<<grid, 256, SM128>>>(
            q, wh + 0 * WSZ, wl + 0 * WSZ, bq, qp, nullptr, nullptr,
            D_, D_, D_, D_, 0,0,0,0,0,0, 1, 1.0f);
        gemm_mma<128,1><<<grid, 256, SM128>>>(
            k, wh + 1 * WSZ, wl + 1 * WSZ, bk, nullptr, kh, kl,
            D_, D_, D_, D_, 0,0,0,0,0,0, 1, 1.0f);
        gemm_mma<128,2><<<grid, 256, SM128>>>(
            v, wh + 2 * WSZ, wl + 2 * WSZ, bv, nullptr, vth, vtl,
            D_, D_, D_, D_, 0,0,0,0,0,0, 1, 1.0f);
    }

    // 2) Logits: attn[b,h,i,j] = scale * dot(Qp[b,i,h*64:], Kh/l[b,j,h*64:])
    {
        dim3 grid(S_ / 128, S_ / 128, B_ * H_);
        gemm_mma<128,0><<<grid, 256, SM128>>>(
            qp, kh, kl, nullptr, attn, nullptr, nullptr,
            DK_, D_, D_, S_,
            (long long)S_ * D_, DK_,
            (long long)S_ * D_, DK_,
            (long long)H_ * S_ * S_, (long long)S_ * S_,
            H_, inv_sqrt_dk);
    }

    // 3) Softmax over last dim, in place
    softmax_rows2048<<<(unsigned)(B_ * H_ * S_), 256>>>(attn);

    // 4) Ctx: ctx[b,s,h*64+d] = sum_j attn[b,h,s,j] * Vt[b,h,d,j]
    {
        dim3 grid(1, S_ / 128, B_ * H_);
        gemm_mma<64,0><<<grid, 256, SM64>>>(
            attn, vth, vtl, nullptr, ctx, nullptr, nullptr,
            S_, S_, S_, D_,
            (long long)H_ * S_ * S_, (long long)S_ * S_,
            (long long)H_ * DK_ * S_, (long long)DK_ * S_,
            (long long)S_ * D_, (long long)DK_,
            H_, 1.0f);
    }

    // 5) Output projection: out = ctx @ Wo^T + bo
    {
        dim3 grid(D_ / 128, (int)(BS_LL / 128), 1);
        gemm_mma<128,0><<<grid, 256, SM128>>>(
            ctx, wh + 3 * WSZ, wl + 3 * WSZ, bo, out, nullptr, nullptr,
            D_, D_, D_, D_, 0,0,0,0,0,0, 1, 1.0f);
    }
}